// round 1
// baseline (speedup 1.0000x reference)
#include <cuda_runtime.h>
#include <cuda_bf16.h>

// YOLO loss: N=64, S=128, B=2.
// input  (N,S,S,10) fp32, target (N,S,S,5) fp32
// out: 5 fp32 scalars (loss, loss_noobj, loss_xy, loss_wh, loss_obj)

#define NCELLS (64 * 128 * 128)
#define THREADS 256
#define NWARPS (THREADS / 32)

// Accumulators: 0:S_noobj 1:S_xy 2:S_wh 3:S_obj 4:S_nresp 5:m
__device__ float g_acc[6];

__global__ void yolo_zero_kernel() {
    if (threadIdx.x < 6) g_acc[threadIdx.x] = 0.0f;
}

__device__ __forceinline__ float sigmoidf(float x) {
    return 1.0f / (1.0f + __expf(-x));
}
// logaddexp(0, x) = softplus(x), numerically stable
__device__ __forceinline__ float softplusf(float x) {
    return fmaxf(x, 0.0f) + log1pf(__expf(-fabsf(x)));
}

__device__ __forceinline__ float iou_box(float cx, float cy, float cw, float ch,
                                         float tlx, float tly, float trx, float tryy,
                                         float area_t) {
    float plx = cx - cw * 0.5f;
    float ply = cy - ch * 0.5f;
    float prx = cx + cw * 0.5f;
    float pry = cy + ch * 0.5f;
    float wx = fmaxf(0.0f, fminf(prx, trx) - fmaxf(plx, tlx));
    float wy = fmaxf(0.0f, fminf(pry, tryy) - fmaxf(ply, tly));
    float inter = wx * wy;
    return inter / (cw * ch + area_t - inter + 1e-10f);
}

__global__ void __launch_bounds__(THREADS)
yolo_main_kernel(const float* __restrict__ inp, const float* __restrict__ tgt) {
    int i = blockIdx.x * blockDim.x + threadIdx.x;

    float s_noobj = 0.0f, s_xy = 0.0f, s_wh = 0.0f;
    float s_obj = 0.0f, s_nresp = 0.0f, s_m = 0.0f;

    if (i < NCELLS) {
        // 10 floats per cell, stride 40B -> always 8B aligned: 5x float2
        const float2* p = reinterpret_cast<const float2*>(inp) + (size_t)i * 5;
        float2 a0 = p[0];
        float2 a1 = p[1];
        float2 a2 = p[2];
        float2 a3 = p[3];
        float2 a4 = p[4];

        const float* t = tgt + (size_t)i * 5;
        float tconf = t[0];
        float tx = t[1], ty = t[2], tw = t[3], th = t[4];

        float l0 = a0.x;
        float l1 = a2.y;
        float bce0_0 = softplusf(l0);
        float bce0_1 = softplusf(l1);

        if (!(tconf > 0.0f)) {
            // no-object cell: both boxes contribute bce0 to noobj loss
            s_noobj = bce0_0 + bce0_1;
        } else {
            s_m = 1.0f;
            float c0x = sigmoidf(a0.y), c0y = sigmoidf(a1.x);
            float c0w = sigmoidf(a1.y), c0h = sigmoidf(a2.x);
            float c1x = sigmoidf(a3.x), c1y = sigmoidf(a3.y);
            float c1w = sigmoidf(a4.x), c1h = sigmoidf(a4.y);

            float tlx = tx - tw * 0.5f, tly = ty - th * 0.5f;
            float trx = tx + tw * 0.5f, tryy = ty + th * 0.5f;
            float area_t = tw * th;

            float iou0 = iou_box(c0x, c0y, c0w, c0h, tlx, tly, trx, tryy, area_t);
            float iou1 = iou_box(c1x, c1y, c1w, c1h, tlx, tly, trx, tryy, area_t);

            // jnp.argmax: first max wins -> box 1 only if strictly greater
            if (iou1 > iou0) {
                float dx = c1x - tx, dy = c1y - ty, dw = c1w - tw, dh = c1h - th;
                s_xy = dx * dx + dy * dy;
                s_wh = dw * dw + dh * dh;
                s_obj = bce0_1 - l1;   // bce1 of responsible box
                s_nresp = bce0_0;      // bce0 of non-responsible box
            } else {
                float dx = c0x - tx, dy = c0y - ty, dw = c0w - tw, dh = c0h - th;
                s_xy = dx * dx + dy * dy;
                s_wh = dw * dw + dh * dh;
                s_obj = bce0_0 - l0;
                s_nresp = bce0_1;
            }
        }
    }

    // ---- block reduction: warp shuffle, then shared across warps ----
    float v[6] = {s_noobj, s_xy, s_wh, s_obj, s_nresp, s_m};
#pragma unroll
    for (int k = 0; k < 6; k++) {
#pragma unroll
        for (int off = 16; off > 0; off >>= 1)
            v[k] += __shfl_xor_sync(0xffffffffu, v[k], off);
    }

    __shared__ float sh[NWARPS][6];
    int lane = threadIdx.x & 31;
    int warp = threadIdx.x >> 5;
    if (lane == 0) {
#pragma unroll
        for (int k = 0; k < 6; k++) sh[warp][k] = v[k];
    }
    __syncthreads();

    if (warp == 0) {
        float w[6];
#pragma unroll
        for (int k = 0; k < 6; k++)
            w[k] = (lane < NWARPS) ? sh[lane][k] : 0.0f;
#pragma unroll
        for (int k = 0; k < 6; k++) {
#pragma unroll
            for (int off = NWARPS / 2; off > 0; off >>= 1)
                w[k] += __shfl_xor_sync(0xffffffffu, w[k], off);
        }
        if (lane == 0) {
#pragma unroll
            for (int k = 0; k < 6; k++) atomicAdd(&g_acc[k], w[k]);
        }
    }
}

__global__ void yolo_finalize_kernel(float* __restrict__ out) {
    if (threadIdx.x == 0) {
        float m = g_acc[5];
        float n_noobj = (float)NCELLS - m;
        // B = 2 -> noobj denom n_noobj*B ; nresp denom m*(B-1) = m
        float loss_noobj = g_acc[0] / (n_noobj * 2.0f) + g_acc[4] / m;
        float loss_xy = g_acc[1] / (m * 2.0f);
        float loss_wh = g_acc[2] / (m * 2.0f);
        float loss_obj = g_acc[3] / m;
        float loss = loss_noobj + loss_xy + loss_wh + loss_obj;
        out[0] = loss;
        out[1] = loss_noobj;
        out[2] = loss_xy;
        out[3] = loss_wh;
        out[4] = loss_obj;
    }
}

extern "C" void kernel_launch(void* const* d_in, const int* in_sizes, int n_in,
                              void* d_out, int out_size) {
    const float* inp = (const float*)d_in[0];
    const float* tgt = (const float*)d_in[1];
    float* out = (float*)d_out;

    yolo_zero_kernel<<<1, 32>>>();
    int blocks = (NCELLS + THREADS - 1) / THREADS;
    yolo_main_kernel<<<blocks, THREADS>>>(inp, tgt);
    yolo_finalize_kernel<<<1, 32>>>(out);
}

// round 2
// speedup vs baseline: 1.7296x; 1.7296x over previous
#include <cuda_runtime.h>
#include <cuda_bf16.h>

// YOLO loss: N=64, S=128, B=2.
// input (N,S,S,10) fp32, target (N,S,S,5) fp32 -> 5 fp32 scalars.
// Single fused kernel: grid reduction via atomics + last-block finalize.

#define NCELLS (64 * 128 * 128)
#define THREADS 256
#define NWARPS (THREADS / 32)
// each thread processes a PAIR of cells: 2048 blocks x 256 threads x 2 = NCELLS
#define BLOCKS (NCELLS / (THREADS * 2))

// zero-initialized at module load; last block resets them for the next replay
__device__ float g_acc[6];        // 0:S_noobj 1:S_xy 2:S_wh 3:S_obj 4:S_nresp 5:m
__device__ unsigned int g_count;

__device__ __forceinline__ float softplus_fast(float x) {
    // logaddexp(0,x), stable, MUFU-based
    return fmaxf(x, 0.0f) + __logf(1.0f + __expf(-fabsf(x)));
}
__device__ __forceinline__ float sigmoid_fast(float x) {
    return __fdividef(1.0f, 1.0f + __expf(-x));
}

// Process one cell; accumulates the 6 partial sums.
__device__ __forceinline__ void process_cell(
    float l0, float x0, float y0, float w0, float h0,
    float l1, float x1, float y1, float w1, float h1,
    float tconf, float tx, float ty, float tw, float th,
    float& s_noobj, float& s_xy, float& s_wh,
    float& s_obj, float& s_nresp, float& s_m)
{
    float bce0_0 = softplus_fast(l0);
    float bce0_1 = softplus_fast(l1);

    if (!(tconf > 0.0f)) {
        s_noobj += bce0_0 + bce0_1;
        return;
    }
    s_m += 1.0f;

    float c0x = sigmoid_fast(x0), c0y = sigmoid_fast(y0);
    float c0w = sigmoid_fast(w0), c0h = sigmoid_fast(h0);
    float c1x = sigmoid_fast(x1), c1y = sigmoid_fast(y1);
    float c1w = sigmoid_fast(w1), c1h = sigmoid_fast(h1);

    float tlx = tx - tw * 0.5f, tly = ty - th * 0.5f;
    float trx = tx + tw * 0.5f, trY = ty + th * 0.5f;
    float area_t = tw * th;

    // box 0 intersection / denominator
    float wx0 = fmaxf(0.0f, fminf(c0x + c0w * 0.5f, trx) - fmaxf(c0x - c0w * 0.5f, tlx));
    float wy0 = fmaxf(0.0f, fminf(c0y + c0h * 0.5f, trY) - fmaxf(c0y - c0h * 0.5f, tly));
    float inter0 = wx0 * wy0;
    float den0 = c0w * c0h + area_t - inter0 + 1e-10f;
    // box 1
    float wx1 = fmaxf(0.0f, fminf(c1x + c1w * 0.5f, trx) - fmaxf(c1x - c1w * 0.5f, tlx));
    float wy1 = fmaxf(0.0f, fminf(c1y + c1h * 0.5f, trY) - fmaxf(c1y - c1h * 0.5f, tly));
    float inter1 = wx1 * wy1;
    float den1 = c1w * c1h + area_t - inter1 + 1e-10f;

    // argmax(iou): box1 responsible iff iou1 > iou0 (first max wins on ties).
    // dens > 0 so compare cross-products -> no division needed.
    bool resp1 = inter1 * den0 > inter0 * den1;

    float rx, ry, rw, rh, rl, rbce0, nbce0;
    if (resp1) {
        rx = c1x; ry = c1y; rw = c1w; rh = c1h; rl = l1; rbce0 = bce0_1; nbce0 = bce0_0;
    } else {
        rx = c0x; ry = c0y; rw = c0w; rh = c0h; rl = l0; rbce0 = bce0_0; nbce0 = bce0_1;
    }
    float dx = rx - tx, dy = ry - ty, dw = rw - tw, dh = rh - th;
    s_xy += dx * dx + dy * dy;
    s_wh += dw * dw + dh * dh;
    s_obj += rbce0 - rl;   // bce1 of responsible box
    s_nresp += nbce0;      // bce0 of non-responsible box
}

__global__ void __launch_bounds__(THREADS)
yolo_fused_kernel(const float4* __restrict__ inp4, const float2* __restrict__ tgt2,
                  float* __restrict__ out) {
    int t = blockIdx.x * THREADS + threadIdx.x;   // pair index, exact coverage

    // ---- vector loads: 2 cells input = 5x float4, 2 cells target = 5x float2 ----
    const float4* ip = inp4 + (size_t)t * 5;
    float4 i0 = ip[0], i1 = ip[1], i2 = ip[2], i3 = ip[3], i4 = ip[4];
    const float2* tp = tgt2 + (size_t)t * 5;
    float2 t0 = tp[0], t1 = tp[1], t2 = tp[2], t3 = tp[3], t4 = tp[4];

    float s_noobj = 0.0f, s_xy = 0.0f, s_wh = 0.0f;
    float s_obj = 0.0f, s_nresp = 0.0f, s_m = 0.0f;

    // cell A: [conf0,x,y,w,h | conf1,x,y,w,h] = i0.x..i2.y ; target t0.x..t2.x
    process_cell(i0.x, i0.y, i0.z, i0.w, i1.x,
                 i1.y, i1.z, i1.w, i2.x, i2.y,
                 t0.x, t0.y, t1.x, t1.y, t2.x,
                 s_noobj, s_xy, s_wh, s_obj, s_nresp, s_m);
    // cell B: i2.z..i4.w ; target t2.y..t4.y
    process_cell(i2.z, i2.w, i3.x, i3.y, i3.z,
                 i3.w, i4.x, i4.y, i4.z, i4.w,
                 t2.y, t3.x, t3.y, t4.x, t4.y,
                 s_noobj, s_xy, s_wh, s_obj, s_nresp, s_m);

    // ---- block reduction ----
    float v[6] = {s_noobj, s_xy, s_wh, s_obj, s_nresp, s_m};
#pragma unroll
    for (int k = 0; k < 6; k++) {
#pragma unroll
        for (int off = 16; off > 0; off >>= 1)
            v[k] += __shfl_xor_sync(0xffffffffu, v[k], off);
    }

    __shared__ float sh[NWARPS][6];
    __shared__ bool is_last;
    int lane = threadIdx.x & 31;
    int warp = threadIdx.x >> 5;
    if (lane == 0) {
#pragma unroll
        for (int k = 0; k < 6; k++) sh[warp][k] = v[k];
    }
    __syncthreads();

    if (warp == 0) {
        float w[6];
#pragma unroll
        for (int k = 0; k < 6; k++)
            w[k] = (lane < NWARPS) ? sh[lane][k] : 0.0f;
#pragma unroll
        for (int k = 0; k < 6; k++) {
#pragma unroll
            for (int off = NWARPS / 2; off > 0; off >>= 1)
                w[k] += __shfl_xor_sync(0xffffffffu, w[k], off);
        }
        if (lane == 0) {
#pragma unroll
            for (int k = 0; k < 6; k++) atomicAdd(&g_acc[k], w[k]);
            __threadfence();
            unsigned int old = atomicAdd(&g_count, 1u);
            is_last = (old == (unsigned int)(gridDim.x - 1));
        }
    }
    __syncthreads();

    // ---- last block finalizes + resets accumulators for the next replay ----
    if (is_last && threadIdx.x == 0) {
        volatile float* ga = g_acc;
        float a_noobj = ga[0], a_xy = ga[1], a_wh = ga[2];
        float a_obj = ga[3], a_nresp = ga[4], m = ga[5];
        float n_noobj = (float)NCELLS - m;
        // B=2: noobj denom = n_noobj*2 ; nresp denom = m*(B-1) = m
        float loss_noobj = a_noobj / (n_noobj * 2.0f) + a_nresp / m;
        float loss_xy = a_xy / (m * 2.0f);
        float loss_wh = a_wh / (m * 2.0f);
        float loss_obj = a_obj / m;
        out[0] = loss_noobj + loss_xy + loss_wh + loss_obj;
        out[1] = loss_noobj;
        out[2] = loss_xy;
        out[3] = loss_wh;
        out[4] = loss_obj;
        // reset for next graph replay
#pragma unroll
        for (int k = 0; k < 6; k++) g_acc[k] = 0.0f;
        g_count = 0u;
    }
}

extern "C" void kernel_launch(void* const* d_in, const int* in_sizes, int n_in,
                              void* d_out, int out_size) {
    const float4* inp4 = (const float4*)d_in[0];
    const float2* tgt2 = (const float2*)d_in[1];
    float* out = (float*)d_out;
    yolo_fused_kernel<<<BLOCKS, THREADS>>>(inp4, tgt2, out);
}

// round 3
// speedup vs baseline: 2.4747x; 1.4307x over previous
#include <cuda_runtime.h>
#include <cuda_bf16.h>

// YOLO loss: N=64, S=128, B=2.
// input (N,S,S,10) fp32, target (N,S,S,5) fp32 -> 5 fp32 scalars.
// Single fused kernel, 4 cells per thread, branchless, grid reduction.

#define NCELLS (64 * 128 * 128)
#define THREADS 256
#define NWARPS (THREADS / 32)
#define NPAIRS (NCELLS / 2)              // 262144 pair-groups (2 cells each)
#define BLOCKS (NPAIRS / (THREADS * 2))  // 512 blocks, 2 pair-groups per thread

// zero-initialized at module load; last block resets them each replay
__device__ float g_acc[6];   // 0:S_noobj 1:S_xy 2:S_wh 3:S_obj 4:S_nresp 5:m
__device__ unsigned int g_count;

__device__ __forceinline__ float softplus_fast(float x) {
    return fmaxf(x, 0.0f) + __logf(1.0f + __expf(-fabsf(x)));
}
__device__ __forceinline__ float sigmoid_fast(float x) {
    return __fdividef(1.0f, 1.0f + __expf(-x));
}

// Branchless single-cell processing (float-mask weighted accumulation).
__device__ __forceinline__ void process_cell(
    float l0, float x0, float y0, float w0, float h0,
    float l1, float x1, float y1, float w1, float h1,
    float tconf, float tx, float ty, float tw, float th,
    float& s_noobj, float& s_xy, float& s_wh,
    float& s_obj, float& s_nresp, float& s_m)
{
    float obj = (tconf > 0.0f) ? 1.0f : 0.0f;
    float noobj = 1.0f - obj;

    float bce0_0 = softplus_fast(l0);
    float bce0_1 = softplus_fast(l1);

    s_noobj += noobj * (bce0_0 + bce0_1);
    s_m += obj;

    float c0x = sigmoid_fast(x0), c0y = sigmoid_fast(y0);
    float c0w = sigmoid_fast(w0), c0h = sigmoid_fast(h0);
    float c1x = sigmoid_fast(x1), c1y = sigmoid_fast(y1);
    float c1w = sigmoid_fast(w1), c1h = sigmoid_fast(h1);

    float tlx = tx - tw * 0.5f, tly = ty - th * 0.5f;
    float trx = tx + tw * 0.5f, trY = ty + th * 0.5f;
    float area_t = tw * th;

    float wx0 = fmaxf(0.0f, fminf(c0x + c0w * 0.5f, trx) - fmaxf(c0x - c0w * 0.5f, tlx));
    float wy0 = fmaxf(0.0f, fminf(c0y + c0h * 0.5f, trY) - fmaxf(c0y - c0h * 0.5f, tly));
    float inter0 = wx0 * wy0;
    float den0 = c0w * c0h + area_t - inter0 + 1e-10f;

    float wx1 = fmaxf(0.0f, fminf(c1x + c1w * 0.5f, trx) - fmaxf(c1x - c1w * 0.5f, tlx));
    float wy1 = fmaxf(0.0f, fminf(c1y + c1h * 0.5f, trY) - fmaxf(c1y - c1h * 0.5f, tly));
    float inter1 = wx1 * wy1;
    float den1 = c1w * c1h + area_t - inter1 + 1e-10f;

    // argmax(iou): box1 wins only if strictly greater (first-max tie-break);
    // denominators > 0 so compare cross-products (no division).
    bool r1 = inter1 * den0 > inter0 * den1;

    float rx = r1 ? c1x : c0x, ry = r1 ? c1y : c0y;
    float rw = r1 ? c1w : c0w, rh = r1 ? c1h : c0h;
    float rl = r1 ? l1 : l0;
    float rb = r1 ? bce0_1 : bce0_0;
    float nb = r1 ? bce0_0 : bce0_1;

    float dx = rx - tx, dy = ry - ty, dw = rw - tw, dh = rh - th;
    s_xy    += obj * (dx * dx + dy * dy);
    s_wh    += obj * (dw * dw + dh * dh);
    s_obj   += obj * (rb - rl);   // bce1 of responsible box
    s_nresp += obj * nb;          // bce0 of non-responsible box
}

// Process a pair-group (2 cells) from pre-loaded registers.
__device__ __forceinline__ void process_pair(
    const float4& i0, const float4& i1, const float4& i2,
    const float4& i3, const float4& i4,
    const float2& t0, const float2& t1, const float2& t2,
    const float2& t3, const float2& t4,
    float& s_noobj, float& s_xy, float& s_wh,
    float& s_obj, float& s_nresp, float& s_m)
{
    process_cell(i0.x, i0.y, i0.z, i0.w, i1.x,
                 i1.y, i1.z, i1.w, i2.x, i2.y,
                 t0.x, t0.y, t1.x, t1.y, t2.x,
                 s_noobj, s_xy, s_wh, s_obj, s_nresp, s_m);
    process_cell(i2.z, i2.w, i3.x, i3.y, i3.z,
                 i3.w, i4.x, i4.y, i4.z, i4.w,
                 t2.y, t3.x, t3.y, t4.x, t4.y,
                 s_noobj, s_xy, s_wh, s_obj, s_nresp, s_m);
}

__global__ void __launch_bounds__(THREADS)
yolo_fused_kernel(const float4* __restrict__ inp4, const float2* __restrict__ tgt2,
                  float* __restrict__ out) {
    // two pair-groups per thread, both coalesced across the block
    int ta = blockIdx.x * (THREADS * 2) + threadIdx.x;
    int tb = ta + THREADS;

    // ---- front-batched loads: 10x LDG.128 + 10x LDG.64 (MLP ~20) ----
    const float4* ipA = inp4 + (size_t)ta * 5;
    const float4* ipB = inp4 + (size_t)tb * 5;
    float4 a0 = ipA[0], a1 = ipA[1], a2 = ipA[2], a3 = ipA[3], a4 = ipA[4];
    float4 b0 = ipB[0], b1 = ipB[1], b2 = ipB[2], b3 = ipB[3], b4 = ipB[4];
    const float2* tpA = tgt2 + (size_t)ta * 5;
    const float2* tpB = tgt2 + (size_t)tb * 5;
    float2 u0 = tpA[0], u1 = tpA[1], u2 = tpA[2], u3 = tpA[3], u4 = tpA[4];
    float2 v0 = tpB[0], v1 = tpB[1], v2 = tpB[2], v3 = tpB[3], v4 = tpB[4];

    float s_noobj = 0.0f, s_xy = 0.0f, s_wh = 0.0f;
    float s_obj = 0.0f, s_nresp = 0.0f, s_m = 0.0f;

    process_pair(a0, a1, a2, a3, a4, u0, u1, u2, u3, u4,
                 s_noobj, s_xy, s_wh, s_obj, s_nresp, s_m);
    process_pair(b0, b1, b2, b3, b4, v0, v1, v2, v3, v4,
                 s_noobj, s_xy, s_wh, s_obj, s_nresp, s_m);

    // ---- warp + block reduction ----
    float v[6] = {s_noobj, s_xy, s_wh, s_obj, s_nresp, s_m};
#pragma unroll
    for (int k = 0; k < 6; k++) {
#pragma unroll
        for (int off = 16; off > 0; off >>= 1)
            v[k] += __shfl_xor_sync(0xffffffffu, v[k], off);
    }

    __shared__ float sh[NWARPS][6];
    __shared__ bool is_last;
    int lane = threadIdx.x & 31;
    int warp = threadIdx.x >> 5;
    if (lane == 0) {
#pragma unroll
        for (int k = 0; k < 6; k++) sh[warp][k] = v[k];
    }
    __syncthreads();

    if (warp == 0) {
        float w[6];
#pragma unroll
        for (int k = 0; k < 6; k++)
            w[k] = (lane < NWARPS) ? sh[lane][k] : 0.0f;
#pragma unroll
        for (int k = 0; k < 6; k++) {
#pragma unroll
            for (int off = NWARPS / 2; off > 0; off >>= 1)
                w[k] += __shfl_xor_sync(0xffffffffu, w[k], off);
        }
        if (lane == 0) {
#pragma unroll
            for (int k = 0; k < 6; k++) atomicAdd(&g_acc[k], w[k]);
            __threadfence();
            unsigned int old = atomicAdd(&g_count, 1u);
            is_last = (old == (unsigned int)(gridDim.x - 1));
        }
    }
    __syncthreads();

    // ---- last block finalizes + resets for the next graph replay ----
    if (is_last && threadIdx.x == 0) {
        volatile float* ga = g_acc;
        float a_noobj = ga[0], a_xy = ga[1], a_wh = ga[2];
        float a_obj = ga[3], a_nresp = ga[4], m = ga[5];
        float n_noobj = (float)NCELLS - m;
        float loss_noobj = a_noobj / (n_noobj * 2.0f) + a_nresp / m;  // B=2
        float loss_xy = a_xy / (m * 2.0f);
        float loss_wh = a_wh / (m * 2.0f);
        float loss_obj = a_obj / m;
        out[0] = loss_noobj + loss_xy + loss_wh + loss_obj;
        out[1] = loss_noobj;
        out[2] = loss_xy;
        out[3] = loss_wh;
        out[4] = loss_obj;
#pragma unroll
        for (int k = 0; k < 6; k++) g_acc[k] = 0.0f;
        g_count = 0u;
    }
}

extern "C" void kernel_launch(void* const* d_in, const int* in_sizes, int n_in,
                              void* d_out, int out_size) {
    const float4* inp4 = (const float4*)d_in[0];
    const float2* tgt2 = (const float2*)d_in[1];
    float* out = (float*)d_out;
    yolo_fused_kernel<<<BLOCKS, THREADS>>>(inp4, tgt2, out);
}